// round 8
// baseline (speedup 1.0000x reference)
#include <cuda_runtime.h>
#include <math.h>
#include <stdint.h>

#define VSZ 50257
#define HD  256
#define ESZ 64
#define TT  2048
#define OUTW 50348   // 2 + 64 + 25 + 50257

typedef unsigned long long ull;

// ---------------- device scratch ----------------
__device__ float g_GX[TT*1024];
__device__ float g_Hmat[TT*HD];
__device__ float g_Ecur[TT*HD];
__device__ float g_Uupd[TT*HD];
__device__ float g_Z[TT*HD];
__device__ float g_D[TT*HD];
__device__ float g_G[TT*HD];
__device__ float g_R2[2*HD];
__device__ float g_wsum[HD];

__device__ __forceinline__ float sigf(float x){ return 1.0f/(1.0f+expf(-x)); }

__device__ __forceinline__ float wredxor(float v){
    #pragma unroll
    for (int o=16;o;o>>=1) v += __shfl_xor_sync(0xffffffffu, v, o);
    return v;
}

__device__ __forceinline__ float bred(float v, float* sred, int tid){
    #pragma unroll
    for (int o=16;o;o>>=1) v += __shfl_down_sync(0xffffffffu, v, o);
    if ((tid&31)==0) sred[tid>>5]=v;
    __syncthreads();
    if (tid==0){ float s=0.f; for(int i=0;i<8;++i) s+=sred[i]; sred[0]=s; }
    __syncthreads();
    float r = sred[0];
    __syncthreads();
    return r;
}

// packed f32x2 helpers
__device__ __forceinline__ ull fma2(ull a, ull b, ull c){
    ull d; asm("fma.rn.f32x2 %0,%1,%2,%3;" : "=l"(d) : "l"(a), "l"(b), "l"(c)); return d;
}
__device__ __forceinline__ ull dup2(float x){
    ull d; unsigned u=__float_as_uint(x);
    asm("mov.b64 %0,{%1,%1};" : "=l"(d) : "r"(u)); return d;
}
__device__ __forceinline__ float2 unp2(ull a){
    unsigned lo,hi; asm("mov.b64 {%0,%1},%2;" : "=r"(lo), "=r"(hi) : "l"(a));
    return make_float2(__uint_as_float(lo), __uint_as_float(hi));
}

// ---------------- prep: R2 (for pred_r) and wsum (for pred_e) ----------------
__global__ void k_prep(const float* __restrict__ r_emb, const float* __restrict__ Wr,
                       const float* __restrict__ Went)
{
    const int tid = threadIdx.x;
    float s0=0.f, s1=0.f;
    for (int k=0;k<HD;++k){
        float w = Wr[k*HD + tid];
        s0 += r_emb[k]*w;
        s1 += r_emb[HD+k]*w;
    }
    g_R2[tid] = s0; g_R2[HD+tid] = s1;
    float ws=0.f;
    for (int j=0;j<HD;++j) ws += Went[(size_t)tid*HD + j];
    g_wsum[tid] = ws;
}

// ---------------- GX GEMM: GX[t][row] = W_ih[row]·emb[tok_t] + b_ih + b_hh ----------------
// grid (8, 16): M=1024 rows x N=2048 steps, BM=BN=128, BK=16
__global__ void __launch_bounds__(256) k_gx2(const float* __restrict__ Wih,
                                             const float* __restrict__ emb,
                                             const int*   __restrict__ tokens,
                                             const float* __restrict__ bih,
                                             const float* __restrict__ bhh)
{
    __shared__ __align__(16) float As[16][128];
    __shared__ __align__(16) float Bs[16][128];
    __shared__ int stok[128];
    const int tid = threadIdx.x;
    const int m0 = blockIdx.x*128, n0 = blockIdx.y*128;
    const int tx = tid & 15, ty = tid >> 4;
    if (tid < 128) stok[tid] = tokens[n0 + tid];
    __syncthreads();
    float acc[8][8];
    #pragma unroll
    for (int i=0;i<8;++i)
        #pragma unroll
        for (int j=0;j<8;++j) acc[i][j]=0.f;

    for (int k0 = 0; k0 < HD; k0 += 16){
        #pragma unroll
        for (int l=0;l<2;++l){
            int idx = tid + l*256;
            int r = idx >> 2;
            int kk = (idx & 3) * 4;
            float4 v = *(const float4*)(Wih + (size_t)(m0+r)*HD + k0 + kk);
            As[kk][r]=v.x; As[kk+1][r]=v.y; As[kk+2][r]=v.z; As[kk+3][r]=v.w;
            float4 u = *(const float4*)(emb + (size_t)stok[r]*HD + k0 + kk);
            Bs[kk][r]=u.x; Bs[kk+1][r]=u.y; Bs[kk+2][r]=u.z; Bs[kk+3][r]=u.w;
        }
        __syncthreads();
        #pragma unroll
        for (int k=0;k<16;++k){
            float am[8], bn[8];
            #pragma unroll
            for (int i=0;i<8;++i) am[i]=As[k][ty*8+i];
            #pragma unroll
            for (int j=0;j<8;++j) bn[j]=Bs[k][tx*8+j];
            #pragma unroll
            for (int i=0;i<8;++i)
                #pragma unroll
                for (int j=0;j<8;++j) acc[i][j] += am[i]*bn[j];
        }
        __syncthreads();
    }
    #pragma unroll
    for (int i=0;i<8;++i){
        int row = m0 + ty*8 + i;
        float bias = bih[row] + bhh[row];
        #pragma unroll
        for (int j=0;j<8;++j){
            int t = n0 + tx*8 + j;
            g_GX[(size_t)t*1024 + row] = acc[i][j] + bias;
        }
    }
}

// ---------------- D/G GEMM: [Wdelta;Went](512x256) @ Hmat^T ----------------
// grid (4, 16)
__global__ void __launch_bounds__(256) k_bat2(const float* __restrict__ Wd,
                                              const float* __restrict__ Went)
{
    __shared__ __align__(16) float As[16][128];
    __shared__ __align__(16) float Bs[16][128];
    const int tid = threadIdx.x;
    const int m0 = blockIdx.x*128, n0 = blockIdx.y*128;
    const int tx = tid & 15, ty = tid >> 4;
    float acc[8][8];
    #pragma unroll
    for (int i=0;i<8;++i)
        #pragma unroll
        for (int j=0;j<8;++j) acc[i][j]=0.f;

    for (int k0 = 0; k0 < HD; k0 += 16){
        #pragma unroll
        for (int l=0;l<2;++l){
            int idx = tid + l*256;
            int r = idx >> 2;
            int kk = (idx & 3) * 4;
            int gm = m0 + r;
            const float* arow = (gm < 256) ? (Wd + (size_t)gm*HD)
                                           : (Went + (size_t)(gm-256)*HD);
            float4 v = *(const float4*)(arow + k0 + kk);
            As[kk][r]=v.x; As[kk+1][r]=v.y; As[kk+2][r]=v.z; As[kk+3][r]=v.w;
            float4 u = *(const float4*)(g_Hmat + (size_t)(n0+r)*HD + k0 + kk);
            Bs[kk][r]=u.x; Bs[kk+1][r]=u.y; Bs[kk+2][r]=u.z; Bs[kk+3][r]=u.w;
        }
        __syncthreads();
        #pragma unroll
        for (int k=0;k<16;++k){
            float am[8], bn[8];
            #pragma unroll
            for (int i=0;i<8;++i) am[i]=As[k][ty*8+i];
            #pragma unroll
            for (int j=0;j<8;++j) bn[j]=Bs[k][tx*8+j];
            #pragma unroll
            for (int i=0;i<8;++i)
                #pragma unroll
                for (int j=0;j<8;++j) acc[i][j] += am[i]*bn[j];
        }
        __syncthreads();
    }
    #pragma unroll
    for (int i=0;i<8;++i){
        int r = m0 + ty*8 + i;
        #pragma unroll
        for (int j=0;j<8;++j){
            int t = n0 + tx*8 + j;
            if (r < 256) g_D[(size_t)t*HD + r] = acc[i][j];
            else         g_G[(size_t)t*HD + (r-256)] = acc[i][j];
        }
    }
}

// ---------------- LSTM recurrence: ONE 8-CTA cluster, W in regs, DSMEM h push ----------------
__global__ void __cluster_dims__(8,1,1) __launch_bounds__(512,1)
k_lstm(const float* __restrict__ Whh)
{
    __shared__ __align__(16) float sh[2][HD];
    __shared__ float sgate[128];
    __shared__ float scell[32];
    const int b = blockIdx.x;
    const int tid = threadIdx.x;
    const int row = tid>>2, q = tid&3;          // row 0..127, quarter 0..3
    const int g = row>>5, e = row&31;
    const int grow = g*HD + 32*b + e;           // global gate row (0..1023)

    // W[grow][64q .. 64q+63] as 32 packed f32x2 pairs
    ull w2[32];
    {
        const double2* wp = (const double2*)(Whh + (size_t)grow*HD + 64*q);
        #pragma unroll
        for (int i=0;i<16;++i){
            double2 dv = wp[i];
            w2[2*i]   = __double_as_longlong(dv.x);
            w2[2*i+1] = __double_as_longlong(dv.y);
        }
    }
    if (tid < HD) sh[0][tid] = 0.f;
    if (tid < 32) scell[tid] = 0.f;

    // precompute remote store addresses for h push (threads < 32 only)
    uint32_t dst0[8], dst1[8];
    if (tid < 32){
        uint32_t l0 = (uint32_t)__cvta_generic_to_shared(&sh[0][32*b + tid]);
        uint32_t l1 = (uint32_t)__cvta_generic_to_shared(&sh[1][32*b + tid]);
        #pragma unroll
        for (int r=0;r<8;++r){
            asm("mapa.shared::cluster.u32 %0, %1, %2;" : "=r"(dst0[r]) : "r"(l0), "r"(r));
            asm("mapa.shared::cluster.u32 %0, %1, %2;" : "=r"(dst1[r]) : "r"(l1), "r"(r));
        }
    }
    __syncthreads();
    asm volatile("barrier.cluster.arrive.aligned;" ::: "memory");
    asm volatile("barrier.cluster.wait.aligned;"   ::: "memory");

    for (int t = 0; t < TT; ++t){
        const int cur = t&1;
        float gx = __ldcg(&g_GX[(size_t)t*1024 + grow]);
        // dot: W[grow][64q..] · h[64q..]
        const double2* hp = (const double2*)&sh[cur][64*q];
        ull acc = 0ull;
        #pragma unroll
        for (int i=0;i<16;++i){
            double2 hv = hp[i];
            acc = fma2(w2[2*i],   __double_as_longlong(hv.x), acc);
            acc = fma2(w2[2*i+1], __double_as_longlong(hv.y), acc);
        }
        float2 af = unp2(acc);
        float p = af.x + af.y;
        p += __shfl_down_sync(0xffffffffu, p, 2, 4);
        p += __shfl_down_sync(0xffffffffu, p, 1, 4);
        if (q==0) sgate[row] = p + gx;
        __syncthreads();
        if (tid < 32){
            float gi = sigf(sgate[tid]);
            float gf = sigf(sgate[32+tid]);
            float gg = tanhf(sgate[64+tid]);
            float go = sigf(sgate[96+tid]);
            float c = gf*scell[tid] + gi*gg;
            float h = go*tanhf(c);
            scell[tid] = c;
            g_Hmat[(size_t)t*HD + 32*b + tid] = h;
            unsigned hb = __float_as_uint(h);
            const uint32_t* dst = (cur==0) ? dst1 : dst0;   // write NEXT buffer
            #pragma unroll
            for (int r=0;r<8;++r)
                asm volatile("st.shared::cluster.b32 [%0], %1;" :: "r"(dst[r]), "r"(hb) : "memory");
        }
        asm volatile("barrier.cluster.arrive.aligned;" ::: "memory");
        asm volatile("barrier.cluster.wait.aligned;"   ::: "memory");
    }
}

// ---------------- entity chain: one warp, entity table in smem ----------------
__global__ void k_ent(const float* __restrict__ ents0, const int* __restrict__ eids,
                      const float* __restrict__ WdB)
{
    extern __shared__ float sme[];   // 64 * 256 floats = 64KB
    const int lane = threadIdx.x;
    {
        const float4* src = (const float4*)ents0;
        float4* dst = (float4*)sme;
        for (int i = lane; i < ESZ*HD/4; i += 32) dst[i] = src[i];
    }
    __syncwarp();
    const float wdb = WdB[0];
    int eid = eids[0];
    float Dc[8], hc[8];
    #pragma unroll
    for (int i=0;i<8;++i){
        Dc[i] = g_D[lane + 32*i];
        hc[i] = g_Hmat[lane + 32*i];
    }
    for (int t = 0; t < TT; ++t){
        int neid = 0; float Dn[8], hn[8];
        if (t+1 < TT){
            neid = eids[t+1];
            #pragma unroll
            for (int i=0;i<8;++i){
                Dn[i] = g_D[(size_t)(t+1)*HD + lane + 32*i];
                hn[i] = g_Hmat[(size_t)(t+1)*HD + lane + 32*i];
            }
        }
        float e[8];
        #pragma unroll
        for (int i=0;i<8;++i) e[i] = sme[eid*HD + lane + 32*i];
        float ad=0.f, aeh=0.f, aee=0.f, ahh=0.f;
        #pragma unroll
        for (int i=0;i<8;++i){
            ad  += e[i]*Dc[i];
            aeh += e[i]*hc[i];
            aee += e[i]*e[i];
            ahh += hc[i]*hc[i];
        }
        ad = wredxor(ad); aeh = wredxor(aeh); aee = wredxor(aee); ahh = wredxor(ahh);
        float d = sigf(ad + wdb), omd = 1.0f - d;
        float nrm = rsqrtf(d*d*aee + 2.0f*d*omd*aeh + omd*omd*ahh);
        #pragma unroll
        for (int i=0;i<8;++i){
            int k = lane + 32*i;
            float u = (d*e[i] + omd*hc[i]) * nrm;
            sme[eid*HD + k] = u;
            g_Uupd[(size_t)t*HD + k] = u;
            g_Ecur[(size_t)t*HD + k] = e[i];
        }
        __syncwarp();
        eid = neid;
        #pragma unroll
        for (int i=0;i<8;++i){ Dc[i]=Dn[i]; hc[i]=hn[i]; }
    }
}

// ---------------- pred_e: 64 one-warp CTAs; entity e walks its version history ----------------
__global__ void k_prede(const float* __restrict__ ents0, const int* __restrict__ eids,
                        const float* __restrict__ wdW, const float* __restrict__ wdB,
                        const float* __restrict__ WentB, float* __restrict__ out)
{
    const int e = blockIdx.x, lane = threadIdx.x;
    const float wd = wdW[0], db = wdB[0], wb = WentB[0];
    float ek[8], ws[8];
    #pragma unroll
    for (int i=0;i<8;++i){
        ek[i] = ents0[(size_t)e*HD + lane + 32*i];
        ws[i] = g_wsum[lane + 32*i];
    }
    float p = 0.f;
    #pragma unroll
    for (int i=0;i<8;++i) p += ek[i]*ws[i];
    p = wredxor(p);
    float dist = 0.f;
    int eidc = eids[0];
    float Gc[8];
    #pragma unroll
    for (int i=0;i<8;++i) Gc[i] = g_G[lane + 32*i];
    for (int t = 0; t < TT; ++t){
        int eidn = 0; float Gn[8];
        if (t+1 < TT){
            eidn = eids[t+1];
            #pragma unroll
            for (int i=0;i<8;++i) Gn[i] = g_G[(size_t)(t+1)*HD + lane + 32*i];
        }
        float q = 0.f;
        #pragma unroll
        for (int i=0;i<8;++i) q += ek[i]*Gc[i];
        q = wredxor(q);
        if (lane==0)
            out[(size_t)t*OUTW + 2 + e] = q + ((dist - (float)t)*wd + db)*p + wb;
        if (eidc == e){
            float pp = 0.f;
            #pragma unroll
            for (int i=0;i<8;++i){
                ek[i] = g_Uupd[(size_t)t*HD + lane + 32*i];
                pp += ek[i]*ws[i];
            }
            p = wredxor(pp);
            dist = (float)t;
        }
        eidc = eidn;
        #pragma unroll
        for (int i=0;i<8;++i) Gc[i] = Gn[i];
    }
}

// ---------------- Z = h + We@ecur + We_b ; pred_l ; pred_r ----------------
__global__ void __launch_bounds__(256) k_z(const float* __restrict__ We,
                                           const float* __restrict__ Web,
                                           const float* __restrict__ Wlen,
                                           const float* __restrict__ WlenB,
                                           const float* __restrict__ WrB,
                                           float* __restrict__ out)
{
    __shared__ float sx[HD];
    __shared__ float shh[HD];
    __shared__ float sred[8];
    const int tid = threadIdx.x, t = blockIdx.x;
    const int w = tid>>5, lane = tid&31;
    sx[tid]  = g_Ecur[(size_t)t*HD + tid];
    shh[tid] = g_Hmat[(size_t)t*HD + tid];
    __syncthreads();
    #pragma unroll 1
    for (int rr=0;rr<32;++rr){
        int r = w*32 + rr;
        float p = 0.f;
        #pragma unroll
        for (int i=0;i<8;++i){
            int k = lane + 32*i;
            p += We[(size_t)r*HD + k]*sx[k];
        }
        #pragma unroll
        for (int o=16;o;o>>=1) p += __shfl_down_sync(0xffffffffu,p,o);
        if (lane==0)
            g_Z[(size_t)t*HD + r] = p + shh[r] + Web[r];
    }
    for (int l = w; l < 25; l += 8){
        float p = 0.f;
        #pragma unroll
        for (int i=0;i<16;++i){
            int idx = lane + 32*i;
            float x = (idx < HD) ? shh[idx] : sx[idx-HD];
            p += Wlen[(size_t)l*512 + idx]*x;
        }
        #pragma unroll
        for (int o=16;o;o>>=1) p += __shfl_down_sync(0xffffffffu,p,o);
        if (lane==0) out[(size_t)t*OUTW + 66 + l] = p + WlenB[l];
    }
    float v = shh[tid];
    float p0 = bred(g_R2[tid]*v, sred, tid);
    float p1 = bred(g_R2[HD+tid]*v, sred, tid);
    if (tid==0){
        out[(size_t)t*OUTW + 0] = p0 + WrB[0];
        out[(size_t)t*OUTW + 1] = p1 + WrB[0];
    }
}

// ---------------- logits GEMM with packed f32x2 FMA ----------------
#define BM 128
#define BN 128
#define BK 16
__global__ void __launch_bounds__(256) k_out(const float* __restrict__ W,
                                             const float* __restrict__ ob,
                                             float* __restrict__ out)
{
    __shared__ __align__(16) float As[BK][BM];
    __shared__ __align__(16) float Bs[BK][BN];
    const int tid = threadIdx.x;
    const int m0 = blockIdx.x*BM, n0 = blockIdx.y*BN;
    const int tx = tid & 15, ty = tid >> 4;
    ull acc2[8][4];
    #pragma unroll
    for (int i=0;i<8;++i)
        #pragma unroll
        for (int jp=0;jp<4;++jp) acc2[i][jp]=0ull;

    for (int k0 = 0; k0 < HD; k0 += BK){
        #pragma unroll
        for (int l=0;l<2;++l){
            int idx = tid + l*256;
            int r = idx >> 2;
            int kk = (idx & 3) * 4;
            int gm = m0 + r;
            float4 v = (gm < VSZ) ? *(const float4*)(W + (size_t)gm*HD + k0 + kk)
                                  : make_float4(0.f,0.f,0.f,0.f);
            As[kk][r]=v.x; As[kk+1][r]=v.y; As[kk+2][r]=v.z; As[kk+3][r]=v.w;
            float4 u = *(const float4*)(g_Z + (size_t)(n0+r)*HD + k0 + kk);
            Bs[kk][r]=u.x; Bs[kk+1][r]=u.y; Bs[kk+2][r]=u.z; Bs[kk+3][r]=u.w;
        }
        __syncthreads();
        #pragma unroll
        for (int k=0;k<BK;++k){
            float4 amA = *(const float4*)&As[k][ty*8];
            float4 amB = *(const float4*)&As[k][ty*8+4];
            ull a2[8];
            a2[0]=dup2(amA.x); a2[1]=dup2(amA.y); a2[2]=dup2(amA.z); a2[3]=dup2(amA.w);
            a2[4]=dup2(amB.x); a2[5]=dup2(amB.y); a2[6]=dup2(amB.z); a2[7]=dup2(amB.w);
            double2 b01 = *(const double2*)&Bs[k][tx*8];
            double2 b23 = *(const double2*)&Bs[k][tx*8+4];
            ull b2[4];
            b2[0]=__double_as_longlong(b01.x); b2[1]=__double_as_longlong(b01.y);
            b2[2]=__double_as_longlong(b23.x); b2[3]=__double_as_longlong(b23.y);
            #pragma unroll
            for (int i=0;i<8;++i)
                #pragma unroll
                for (int jp=0;jp<4;++jp)
                    acc2[i][jp] = fma2(a2[i], b2[jp], acc2[i][jp]);
        }
        __syncthreads();
    }
    #pragma unroll
    for (int i=0;i<8;++i){
        int v = m0 + ty*8 + i;
        if (v >= VSZ) continue;
        float bias = ob[v];
        #pragma unroll
        for (int jp=0;jp<4;++jp){
            float2 f = unp2(acc2[i][jp]);
            int t0 = n0 + tx*8 + 2*jp;
            out[(size_t)t0*OUTW + 91 + v]     = f.x + bias;
            out[(size_t)(t0+1)*OUTW + 91 + v] = f.y + bias;
        }
    }
}

extern "C" void kernel_launch(void* const* d_in, const int* in_sizes, int n_in,
                              void* d_out, int out_size)
{
    const int*   tokens  = (const int*)  d_in[0];
    const int*   eids    = (const int*)  d_in[1];
    const float* emb     = (const float*)d_in[2];
    const float* W_ih    = (const float*)d_in[3];
    const float* W_hh    = (const float*)d_in[4];
    const float* b_ih    = (const float*)d_in[5];
    const float* b_hh    = (const float*)d_in[6];
    const float* out_W   = (const float*)d_in[7];
    const float* out_b   = (const float*)d_in[8];
    const float* r_emb   = (const float*)d_in[9];
    const float* Wr_W    = (const float*)d_in[10];
    const float* Wr_b    = (const float*)d_in[11];
    const float* Wlen_W  = (const float*)d_in[12];
    const float* Wlen_b  = (const float*)d_in[13];
    const float* Went_W  = (const float*)d_in[14];
    const float* Went_b  = (const float*)d_in[15];
    const float* wdist_W = (const float*)d_in[16];
    const float* wdist_b = (const float*)d_in[17];
    const float* Wdelta_W= (const float*)d_in[18];
    const float* Wdelta_b= (const float*)d_in[19];
    const float* We_W    = (const float*)d_in[20];
    const float* We_b    = (const float*)d_in[21];
    const float* ents0   = (const float*)d_in[22];
    float* out = (float*)d_out;

    static int smem_set = 0;
    if (!smem_set){
        cudaFuncSetAttribute(k_ent, cudaFuncAttributeMaxDynamicSharedMemorySize, 65536);
        smem_set = 1;
    }

    k_prep<<<1, 256>>>(r_emb, Wr_W, Went_W);
    k_gx2<<<dim3(8,16), 256>>>(W_ih, emb, tokens, b_ih, b_hh);
    k_lstm<<<8, 512>>>(W_hh);
    k_bat2<<<dim3(4,16), 256>>>(Wdelta_W, Went_W);
    k_ent<<<1, 32, 65536>>>(ents0, eids, Wdelta_b);
    k_prede<<<ESZ, 32>>>(ents0, eids, wdist_W, wdist_b, Went_b, out);
    k_z<<<TT, 256>>>(We_W, We_b, Wlen_W, Wlen_b, Wr_b, out);
    dim3 gg((VSZ + BM - 1)/BM, TT/BN);
    k_out<<<gg, 256>>>(out_W, out_b, out);
}

// round 9
// speedup vs baseline: 1.3581x; 1.3581x over previous
#include <cuda_runtime.h>
#include <math.h>
#include <stdint.h>

#define VSZ 50257
#define HD  256
#define ESZ 64
#define TT  2048
#define OUTW 50348   // 2 + 64 + 25 + 50257
#define NBL 32       // persistent LSTM CTAs

typedef unsigned long long ull;

// ---------------- device scratch ----------------
__device__ float g_GX[TT*1024];
__device__ float g_Hmat[TT*HD];
__device__ float g_Ecur[TT*HD];
__device__ float g_Uupd[TT*HD];
__device__ float g_Z[TT*HD];
__device__ float g_D[TT*HD];
__device__ float g_G[TT*HD];
__device__ float g_R2[2*HD];
__device__ float g_wsum[HD];
__device__ float g_hbuf[2][HD];
__device__ unsigned g_bar_cnt;
__device__ volatile unsigned g_bar_gen;

__device__ __forceinline__ float sigf(float x){ return 1.0f/(1.0f+expf(-x)); }

__device__ __forceinline__ float wredxor(float v){
    #pragma unroll
    for (int o=16;o;o>>=1) v += __shfl_xor_sync(0xffffffffu, v, o);
    return v;
}

__device__ __forceinline__ float bred(float v, float* sred, int tid){
    #pragma unroll
    for (int o=16;o;o>>=1) v += __shfl_down_sync(0xffffffffu, v, o);
    if ((tid&31)==0) sred[tid>>5]=v;
    __syncthreads();
    if (tid==0){ float s=0.f; for(int i=0;i<8;++i) s+=sred[i]; sred[0]=s; }
    __syncthreads();
    float r = sred[0];
    __syncthreads();
    return r;
}

// packed f32x2 helpers
__device__ __forceinline__ ull fma2(ull a, ull b, ull c){
    ull d; asm("fma.rn.f32x2 %0,%1,%2,%3;" : "=l"(d) : "l"(a), "l"(b), "l"(c)); return d;
}
__device__ __forceinline__ ull dup2(float x){
    ull d; unsigned u=__float_as_uint(x);
    asm("mov.b64 %0,{%1,%1};" : "=l"(d) : "r"(u)); return d;
}
__device__ __forceinline__ float2 unp2(ull a){
    unsigned lo,hi; asm("mov.b64 {%0,%1},%2;" : "=r"(lo), "=r"(hi) : "l"(a));
    return make_float2(__uint_as_float(lo), __uint_as_float(hi));
}

// ---------------- prep: R2, wsum, hbuf/barrier reset ----------------
__global__ void k_prep(const float* __restrict__ r_emb, const float* __restrict__ Wr,
                       const float* __restrict__ Went)
{
    const int tid = threadIdx.x;
    float s0=0.f, s1=0.f;
    for (int k=0;k<HD;++k){
        float w = Wr[k*HD + tid];
        s0 += r_emb[k]*w;
        s1 += r_emb[HD+k]*w;
    }
    g_R2[tid] = s0; g_R2[HD+tid] = s1;
    float ws=0.f;
    for (int j=0;j<HD;++j) ws += Went[(size_t)tid*HD + j];
    g_wsum[tid] = ws;
    g_hbuf[0][tid] = 0.f; g_hbuf[1][tid] = 0.f;
    if (tid==0){ g_bar_cnt=0u; g_bar_gen=0u; }
}

// ---------------- GX GEMM: GX[t][row] = W_ih[row]·emb[tok_t] + b_ih + b_hh ----------------
// grid (8, 16): M=1024 rows x N=2048 steps, BM=BN=128, BK=16
__global__ void __launch_bounds__(256) k_gx2(const float* __restrict__ Wih,
                                             const float* __restrict__ emb,
                                             const int*   __restrict__ tokens,
                                             const float* __restrict__ bih,
                                             const float* __restrict__ bhh)
{
    __shared__ __align__(16) float As[16][128];
    __shared__ __align__(16) float Bs[16][128];
    __shared__ int stok[128];
    const int tid = threadIdx.x;
    const int m0 = blockIdx.x*128, n0 = blockIdx.y*128;
    const int tx = tid & 15, ty = tid >> 4;
    if (tid < 128) stok[tid] = tokens[n0 + tid];
    __syncthreads();
    float acc[8][8];
    #pragma unroll
    for (int i=0;i<8;++i)
        #pragma unroll
        for (int j=0;j<8;++j) acc[i][j]=0.f;

    for (int k0 = 0; k0 < HD; k0 += 16){
        #pragma unroll
        for (int l=0;l<2;++l){
            int idx = tid + l*256;
            int r = idx >> 2;
            int kk = (idx & 3) * 4;
            float4 v = *(const float4*)(Wih + (size_t)(m0+r)*HD + k0 + kk);
            As[kk][r]=v.x; As[kk+1][r]=v.y; As[kk+2][r]=v.z; As[kk+3][r]=v.w;
            float4 u = *(const float4*)(emb + (size_t)stok[r]*HD + k0 + kk);
            Bs[kk][r]=u.x; Bs[kk+1][r]=u.y; Bs[kk+2][r]=u.z; Bs[kk+3][r]=u.w;
        }
        __syncthreads();
        #pragma unroll
        for (int k=0;k<16;++k){
            float am[8], bn[8];
            #pragma unroll
            for (int i=0;i<8;++i) am[i]=As[k][ty*8+i];
            #pragma unroll
            for (int j=0;j<8;++j) bn[j]=Bs[k][tx*8+j];
            #pragma unroll
            for (int i=0;i<8;++i)
                #pragma unroll
                for (int j=0;j<8;++j) acc[i][j] += am[i]*bn[j];
        }
        __syncthreads();
    }
    #pragma unroll
    for (int i=0;i<8;++i){
        int row = m0 + ty*8 + i;
        float bias = bih[row] + bhh[row];
        #pragma unroll
        for (int j=0;j<8;++j){
            int t = n0 + tx*8 + j;
            g_GX[(size_t)t*1024 + row] = acc[i][j] + bias;
        }
    }
}

// ---------------- D/G GEMM: [Wdelta;Went](512x256) @ Hmat^T ----------------
// grid (4, 16)
__global__ void __launch_bounds__(256) k_bat2(const float* __restrict__ Wd,
                                              const float* __restrict__ Went)
{
    __shared__ __align__(16) float As[16][128];
    __shared__ __align__(16) float Bs[16][128];
    const int tid = threadIdx.x;
    const int m0 = blockIdx.x*128, n0 = blockIdx.y*128;
    const int tx = tid & 15, ty = tid >> 4;
    float acc[8][8];
    #pragma unroll
    for (int i=0;i<8;++i)
        #pragma unroll
        for (int j=0;j<8;++j) acc[i][j]=0.f;

    for (int k0 = 0; k0 < HD; k0 += 16){
        #pragma unroll
        for (int l=0;l<2;++l){
            int idx = tid + l*256;
            int r = idx >> 2;
            int kk = (idx & 3) * 4;
            int gm = m0 + r;
            const float* arow = (gm < 256) ? (Wd + (size_t)gm*HD)
                                           : (Went + (size_t)(gm-256)*HD);
            float4 v = *(const float4*)(arow + k0 + kk);
            As[kk][r]=v.x; As[kk+1][r]=v.y; As[kk+2][r]=v.z; As[kk+3][r]=v.w;
            float4 u = *(const float4*)(g_Hmat + (size_t)(n0+r)*HD + k0 + kk);
            Bs[kk][r]=u.x; Bs[kk+1][r]=u.y; Bs[kk+2][r]=u.z; Bs[kk+3][r]=u.w;
        }
        __syncthreads();
        #pragma unroll
        for (int k=0;k<16;++k){
            float am[8], bn[8];
            #pragma unroll
            for (int i=0;i<8;++i) am[i]=As[k][ty*8+i];
            #pragma unroll
            for (int j=0;j<8;++j) bn[j]=Bs[k][tx*8+j];
            #pragma unroll
            for (int i=0;i<8;++i)
                #pragma unroll
                for (int j=0;j<8;++j) acc[i][j] += am[i]*bn[j];
        }
        __syncthreads();
    }
    #pragma unroll
    for (int i=0;i<8;++i){
        int r = m0 + ty*8 + i;
        #pragma unroll
        for (int j=0;j<8;++j){
            int t = n0 + tx*8 + j;
            if (r < 256) g_D[(size_t)t*HD + r] = acc[i][j];
            else         g_G[(size_t)t*HD + (r-256)] = acc[i][j];
        }
    }
}

// ---------------- pure LSTM recurrence: 32 persistent CTAs, 1 barrier/step (round-7 proven) ----------------
__global__ void __launch_bounds__(512) k_lstm(const float* __restrict__ Whh)
{
    __shared__ float sW[32*HD];   // 32 gate rows for this CTA's 8 h-elements
    __shared__ float sh[HD];
    __shared__ float sgate[32];
    __shared__ float sc[8];
    const int b = blockIdx.x, tid = threadIdx.x;

    for (int idx = tid; idx < 32*HD; idx += 512){
        int i = idx>>8, k = idx&255;
        int row = (i>>3)*HD + 8*b + (i&7);      // gate g=i>>3, local elem jj=i&7
        sW[idx] = Whh[(size_t)row*HD + k];
    }
    if (tid < 8) sc[tid] = 0.f;
    __syncthreads();

    unsigned gen = 0;
    for (int t = 0; t < TT; ++t){
        if (tid < HD) sh[tid] = __ldcg(&g_hbuf[t&1][tid]);
        __syncthreads();
        {
            const int i = tid>>4, kq = tid&15;
            const float* wrow = &sW[i*HD + kq*16];
            const float* hv = &sh[kq*16];
            float p = 0.f;
            #pragma unroll
            for (int j=0;j<16;++j) p += wrow[j]*hv[j];
            #pragma unroll
            for (int o=8;o;o>>=1) p += __shfl_down_sync(0xffffffffu,p,o,16);
            if (kq==0){
                int row = (i>>3)*HD + 8*b + (i&7);
                sgate[i] = p + g_GX[(size_t)t*1024 + row];
            }
        }
        __syncthreads();
        if (tid < 8){
            float gi = sigf(sgate[0*8+tid]);
            float gf = sigf(sgate[1*8+tid]);
            float gg = tanhf(sgate[2*8+tid]);
            float go = sigf(sgate[3*8+tid]);
            float c = gf*sc[tid] + gi*gg;
            float h = go*tanhf(c);
            sc[tid] = c;
            g_hbuf[(t+1)&1][8*b+tid] = h;
            g_Hmat[(size_t)t*HD + 8*b + tid] = h;
        }
        // single grid barrier
        __syncthreads();
        if (tid==0){
            __threadfence();
            unsigned prev = atomicAdd(&g_bar_cnt, 1u);
            if (prev == NBL-1u){ g_bar_cnt = 0u; __threadfence(); g_bar_gen = gen+1u; }
            else { while (g_bar_gen <= gen) {} __threadfence(); }
        }
        __syncthreads();
        ++gen;
    }
}

// ---------------- entity chain: one warp, entity table in smem ----------------
__global__ void k_ent(const float* __restrict__ ents0, const int* __restrict__ eids,
                      const float* __restrict__ WdB)
{
    extern __shared__ float sme[];   // 64 * 256 floats = 64KB
    const int lane = threadIdx.x;
    {
        const float4* src = (const float4*)ents0;
        float4* dst = (float4*)sme;
        for (int i = lane; i < ESZ*HD/4; i += 32) dst[i] = src[i];
    }
    __syncwarp();
    const float wdb = WdB[0];
    int eid = eids[0];
    float Dc[8], hc[8];
    #pragma unroll
    for (int i=0;i<8;++i){
        Dc[i] = g_D[lane + 32*i];
        hc[i] = g_Hmat[lane + 32*i];
    }
    for (int t = 0; t < TT; ++t){
        int neid = 0; float Dn[8], hn[8];
        if (t+1 < TT){
            neid = eids[t+1];
            #pragma unroll
            for (int i=0;i<8;++i){
                Dn[i] = g_D[(size_t)(t+1)*HD + lane + 32*i];
                hn[i] = g_Hmat[(size_t)(t+1)*HD + lane + 32*i];
            }
        }
        float e[8];
        #pragma unroll
        for (int i=0;i<8;++i) e[i] = sme[eid*HD + lane + 32*i];
        float ad=0.f, aeh=0.f, aee=0.f, ahh=0.f;
        #pragma unroll
        for (int i=0;i<8;++i){
            ad  += e[i]*Dc[i];
            aeh += e[i]*hc[i];
            aee += e[i]*e[i];
            ahh += hc[i]*hc[i];
        }
        ad = wredxor(ad); aeh = wredxor(aeh); aee = wredxor(aee); ahh = wredxor(ahh);
        float d = sigf(ad + wdb), omd = 1.0f - d;
        float nrm = rsqrtf(d*d*aee + 2.0f*d*omd*aeh + omd*omd*ahh);
        #pragma unroll
        for (int i=0;i<8;++i){
            int k = lane + 32*i;
            float u = (d*e[i] + omd*hc[i]) * nrm;
            sme[eid*HD + k] = u;
            g_Uupd[(size_t)t*HD + k] = u;
            g_Ecur[(size_t)t*HD + k] = e[i];
        }
        __syncwarp();
        eid = neid;
        #pragma unroll
        for (int i=0;i<8;++i){ Dc[i]=Dn[i]; hc[i]=hn[i]; }
    }
}

// ---------------- pred_e: 64 one-warp CTAs; entity e walks its version history ----------------
__global__ void k_prede(const float* __restrict__ ents0, const int* __restrict__ eids,
                        const float* __restrict__ wdW, const float* __restrict__ wdB,
                        const float* __restrict__ WentB, float* __restrict__ out)
{
    const int e = blockIdx.x, lane = threadIdx.x;
    const float wd = wdW[0], db = wdB[0], wb = WentB[0];
    float ek[8], ws[8];
    #pragma unroll
    for (int i=0;i<8;++i){
        ek[i] = ents0[(size_t)e*HD + lane + 32*i];
        ws[i] = g_wsum[lane + 32*i];
    }
    float p = 0.f;
    #pragma unroll
    for (int i=0;i<8;++i) p += ek[i]*ws[i];
    p = wredxor(p);
    float dist = 0.f;
    int eidc = eids[0];
    float Gc[8];
    #pragma unroll
    for (int i=0;i<8;++i) Gc[i] = g_G[lane + 32*i];
    for (int t = 0; t < TT; ++t){
        int eidn = 0; float Gn[8];
        if (t+1 < TT){
            eidn = eids[t+1];
            #pragma unroll
            for (int i=0;i<8;++i) Gn[i] = g_G[(size_t)(t+1)*HD + lane + 32*i];
        }
        float q = 0.f;
        #pragma unroll
        for (int i=0;i<8;++i) q += ek[i]*Gc[i];
        q = wredxor(q);
        if (lane==0)
            out[(size_t)t*OUTW + 2 + e] = q + ((dist - (float)t)*wd + db)*p + wb;
        if (eidc == e){
            float pp = 0.f;
            #pragma unroll
            for (int i=0;i<8;++i){
                ek[i] = g_Uupd[(size_t)t*HD + lane + 32*i];
                pp += ek[i]*ws[i];
            }
            p = wredxor(pp);
            dist = (float)t;
        }
        eidc = eidn;
        #pragma unroll
        for (int i=0;i<8;++i) Gc[i] = Gn[i];
    }
}

// ---------------- Z = h + We@ecur + We_b ; pred_l ; pred_r ----------------
__global__ void __launch_bounds__(256) k_z(const float* __restrict__ We,
                                           const float* __restrict__ Web,
                                           const float* __restrict__ Wlen,
                                           const float* __restrict__ WlenB,
                                           const float* __restrict__ WrB,
                                           float* __restrict__ out)
{
    __shared__ float sx[HD];
    __shared__ float shh[HD];
    __shared__ float sred[8];
    const int tid = threadIdx.x, t = blockIdx.x;
    const int w = tid>>5, lane = tid&31;
    sx[tid]  = g_Ecur[(size_t)t*HD + tid];
    shh[tid] = g_Hmat[(size_t)t*HD + tid];
    __syncthreads();
    #pragma unroll 1
    for (int rr=0;rr<32;++rr){
        int r = w*32 + rr;
        float p = 0.f;
        #pragma unroll
        for (int i=0;i<8;++i){
            int k = lane + 32*i;
            p += We[(size_t)r*HD + k]*sx[k];
        }
        #pragma unroll
        for (int o=16;o;o>>=1) p += __shfl_down_sync(0xffffffffu,p,o);
        if (lane==0)
            g_Z[(size_t)t*HD + r] = p + shh[r] + Web[r];
    }
    for (int l = w; l < 25; l += 8){
        float p = 0.f;
        #pragma unroll
        for (int i=0;i<16;++i){
            int idx = lane + 32*i;
            float x = (idx < HD) ? shh[idx] : sx[idx-HD];
            p += Wlen[(size_t)l*512 + idx]*x;
        }
        #pragma unroll
        for (int o=16;o;o>>=1) p += __shfl_down_sync(0xffffffffu,p,o);
        if (lane==0) out[(size_t)t*OUTW + 66 + l] = p + WlenB[l];
    }
    float v = shh[tid];
    float p0 = bred(g_R2[tid]*v, sred, tid);
    float p1 = bred(g_R2[HD+tid]*v, sred, tid);
    if (tid==0){
        out[(size_t)t*OUTW + 0] = p0 + WrB[0];
        out[(size_t)t*OUTW + 1] = p1 + WrB[0];
    }
}

// ---------------- logits GEMM with packed f32x2 FMA ----------------
#define BM 128
#define BN 128
#define BK 16
__global__ void __launch_bounds__(256) k_out(const float* __restrict__ W,
                                             const float* __restrict__ ob,
                                             float* __restrict__ out)
{
    __shared__ __align__(16) float As[BK][BM];
    __shared__ __align__(16) float Bs[BK][BN];
    const int tid = threadIdx.x;
    const int m0 = blockIdx.x*BM, n0 = blockIdx.y*BN;
    const int tx = tid & 15, ty = tid >> 4;
    ull acc2[8][4];
    #pragma unroll
    for (int i=0;i<8;++i)
        #pragma unroll
        for (int jp=0;jp<4;++jp) acc2[i][jp]=0ull;

    for (int k0 = 0; k0 < HD; k0 += BK){
        #pragma unroll
        for (int l=0;l<2;++l){
            int idx = tid + l*256;
            int r = idx >> 2;
            int kk = (idx & 3) * 4;
            int gm = m0 + r;
            float4 v = (gm < VSZ) ? *(const float4*)(W + (size_t)gm*HD + k0 + kk)
                                  : make_float4(0.f,0.f,0.f,0.f);
            As[kk][r]=v.x; As[kk+1][r]=v.y; As[kk+2][r]=v.z; As[kk+3][r]=v.w;
            float4 u = *(const float4*)(g_Z + (size_t)(n0+r)*HD + k0 + kk);
            Bs[kk][r]=u.x; Bs[kk+1][r]=u.y; Bs[kk+2][r]=u.z; Bs[kk+3][r]=u.w;
        }
        __syncthreads();
        #pragma unroll
        for (int k=0;k<BK;++k){
            float4 amA = *(const float4*)&As[k][ty*8];
            float4 amB = *(const float4*)&As[k][ty*8+4];
            ull a2[8];
            a2[0]=dup2(amA.x); a2[1]=dup2(amA.y); a2[2]=dup2(amA.z); a2[3]=dup2(amA.w);
            a2[4]=dup2(amB.x); a2[5]=dup2(amB.y); a2[6]=dup2(amB.z); a2[7]=dup2(amB.w);
            double2 b01 = *(const double2*)&Bs[k][tx*8];
            double2 b23 = *(const double2*)&Bs[k][tx*8+4];
            ull b2[4];
            b2[0]=__double_as_longlong(b01.x); b2[1]=__double_as_longlong(b01.y);
            b2[2]=__double_as_longlong(b23.x); b2[3]=__double_as_longlong(b23.y);
            #pragma unroll
            for (int i=0;i<8;++i)
                #pragma unroll
                for (int jp=0;jp<4;++jp)
                    acc2[i][jp] = fma2(a2[i], b2[jp], acc2[i][jp]);
        }
        __syncthreads();
    }
    #pragma unroll
    for (int i=0;i<8;++i){
        int v = m0 + ty*8 + i;
        if (v >= VSZ) continue;
        float bias = ob[v];
        #pragma unroll
        for (int jp=0;jp<4;++jp){
            float2 f = unp2(acc2[i][jp]);
            int t0 = n0 + tx*8 + 2*jp;
            out[(size_t)t0*OUTW + 91 + v]     = f.x + bias;
            out[(size_t)(t0+1)*OUTW + 91 + v] = f.y + bias;
        }
    }
}

extern "C" void kernel_launch(void* const* d_in, const int* in_sizes, int n_in,
                              void* d_out, int out_size)
{
    const int*   tokens  = (const int*)  d_in[0];
    const int*   eids    = (const int*)  d_in[1];
    const float* emb     = (const float*)d_in[2];
    const float* W_ih    = (const float*)d_in[3];
    const float* W_hh    = (const float*)d_in[4];
    const float* b_ih    = (const float*)d_in[5];
    const float* b_hh    = (const float*)d_in[6];
    const float* out_W   = (const float*)d_in[7];
    const float* out_b   = (const float*)d_in[8];
    const float* r_emb   = (const float*)d_in[9];
    const float* Wr_W    = (const float*)d_in[10];
    const float* Wr_b    = (const float*)d_in[11];
    const float* Wlen_W  = (const float*)d_in[12];
    const float* Wlen_b  = (const float*)d_in[13];
    const float* Went_W  = (const float*)d_in[14];
    const float* Went_b  = (const float*)d_in[15];
    const float* wdist_W = (const float*)d_in[16];
    const float* wdist_b = (const float*)d_in[17];
    const float* Wdelta_W= (const float*)d_in[18];
    const float* Wdelta_b= (const float*)d_in[19];
    const float* We_W    = (const float*)d_in[20];
    const float* We_b    = (const float*)d_in[21];
    const float* ents0   = (const float*)d_in[22];
    float* out = (float*)d_out;

    static int smem_set = 0;
    if (!smem_set){
        cudaFuncSetAttribute(k_ent, cudaFuncAttributeMaxDynamicSharedMemorySize, 65536);
        smem_set = 1;
    }

    k_prep<<<1, 256>>>(r_emb, Wr_W, Went_W);
    k_gx2<<<dim3(8,16), 256>>>(W_ih, emb, tokens, b_ih, b_hh);
    k_lstm<<<NBL, 512>>>(W_hh);
    k_bat2<<<dim3(4,16), 256>>>(Wdelta_W, Went_W);
    k_ent<<<1, 32, 65536>>>(ents0, eids, Wdelta_b);
    k_prede<<<ESZ, 32>>>(ents0, eids, wdist_W, wdist_b, Went_b, out);
    k_z<<<TT, 256>>>(We_W, We_b, Wlen_W, Wlen_b, Wr_b, out);
    dim3 gg((VSZ + BM - 1)/BM, TT/BN);
    k_out<<<gg, 256>>>(out_W, out_b, out);
}